// round 15
// baseline (speedup 1.0000x reference)
#include <cuda_runtime.h>
#include <cstdint>

#define HDIM  128
#define WDIM  128
#define N_PIX 16384          // H*W
#define BATCH 64

#define NSM        148
// scan_kernel: capped at 48 regs (launch_bounds min-blocks 5) -> 5 blocks/SM,
// 740 blocks = ONE full co-resident wave (required for the grid barrier).
#define SCAN_BLKS  (NSM * 5)     // 740
#define SEG_CAP    2048          // per-block nonzero segment capacity (mean ~177)

// Scratch (allocation-free __device__ globals). mask/g/counters are all
// rewritten/reset every launch -> self-contained, graph-safe.
__device__ unsigned long long g_spikemask[N_PIX];               // bit b set if S0[b, n] != 0
__device__ float              g_global[BATCH * (size_t)N_PIX];  // g[b][m], 4 MB
__device__ unsigned           g_list_idx[SCAN_BLKS * SEG_CAP];  // flat idx into M
__device__ float              g_list_val[SCAN_BLKS * SEG_CAP];
__device__ int                g_ready;                          // phase-0 barrier (self-resetting)
__device__ int                g_done;                           // reset coordinator

// ---------------------------------------------------------------------------
// Kernel 1 (scan): phase 0 builds the spike mask + zeroes g, publishes via
// g_ready. Phase 1 streams the 1 GiB matrix (256-bit loads) appending
// nonzeros to a per-block segment. Tail: wait for phase-0 barrier (satisfied
// ~160us ago), scatter OWN segment through the mask into g. Scatter hides in
// the inter-block tail skew. Last block resets the counters.
// ---------------------------------------------------------------------------
struct f8 { float v[8]; };

__device__ __forceinline__ f8 load8(const float* __restrict__ p) {
    f8 r;
    asm volatile("ld.global.cs.v8.f32 {%0,%1,%2,%3,%4,%5,%6,%7}, [%8];"
                 : "=f"(r.v[0]), "=f"(r.v[1]), "=f"(r.v[2]), "=f"(r.v[3]),
                   "=f"(r.v[4]), "=f"(r.v[5]), "=f"(r.v[6]), "=f"(r.v[7])
                 : "l"(p));
    return r;
}

__device__ __forceinline__ void append_nz(int* scnt, unsigned seg_base,
                                          size_t idx, float val) {
    int s = atomicAdd(scnt, 1);
    if (s < SEG_CAP) {                       // statically impossible to overflow
        g_list_idx[seg_base + s] = (unsigned)idx;
        g_list_val[seg_base + s] = val;
    }
}

__device__ __forceinline__ void check8(const f8& x, size_t base,
                                       int* scnt, unsigned seg_base) {
    unsigned nz = 0;
    #pragma unroll
    for (int j = 0; j < 8; j++) nz |= __float_as_uint(x.v[j]);
    if (nz != 0u) {
        #pragma unroll
        for (int j = 0; j < 8; j++)
            if (x.v[j] != 0.0f) append_nz(scnt, seg_base, base + j, x.v[j]);
    }
}

__global__ void __launch_bounds__(256, 5) scan_kernel(const float* __restrict__ M,
                                                      const float* __restrict__ S0) {
    __shared__ int scnt;
    if (threadIdx.x == 0) scnt = 0;

    const int tid = blockIdx.x * blockDim.x + threadIdx.x;   // 0..189439
    const int nthreads = gridDim.x * blockDim.x;             // 189,440

    // ---- phase 0a: spike mask (65536 workers, disjoint u16 stores) ----
    if (tid < 4 * N_PIX) {
        int n = tid & (N_PIX - 1);
        int q = tid >> 14;                                   // 16-batch chunk
        const float* base = S0 + (size_t)(q * 16) * N_PIX + n;
        unsigned m16 = 0;
        #pragma unroll
        for (int j = 0; j < 16; j++) {
            float s = __ldg(base + (size_t)j * N_PIX);
            if (s != 0.0f) m16 |= (1u << j);
        }
        reinterpret_cast<unsigned short*>(g_spikemask)[4 * n + q] = (unsigned short)m16;
    }
    // ---- phase 0b: zero g (grid-stride; ~1.4 float4 stores per thread) ----
    for (int i = tid; i < BATCH * N_PIX / 4; i += nthreads)
        reinterpret_cast<float4*>(g_global)[i] = make_float4(0.f, 0.f, 0.f, 0.f);

    // publish phase 0 (release)
    __threadfence();
    __syncthreads();
    if (threadIdx.x == 0) atomicAdd(&g_ready, 1);

    // ---- phase 1: stream M, grid-interleaved, 4 in-flight 32B slots ----
    const unsigned seg_base = blockIdx.x * SEG_CAP;
    const size_t total8 = (size_t)N_PIX * N_PIX / 8;         // 33,554,432
    const size_t stride = (size_t)nthreads;                  // 189,440
    size_t i = (size_t)blockIdx.x * blockDim.x + threadIdx.x;

    for (; i + 3 * stride < total8; i += 4 * stride) {
        f8 a = load8(M + (i)              * 8);
        f8 b = load8(M + (i + stride)     * 8);
        f8 c = load8(M + (i + 2 * stride) * 8);
        f8 d = load8(M + (i + 3 * stride) * 8);
        check8(a, (i)              * 8, &scnt, seg_base);
        check8(b, (i + stride)     * 8, &scnt, seg_base);
        check8(c, (i + 2 * stride) * 8, &scnt, seg_base);
        check8(d, (i + 3 * stride) * 8, &scnt, seg_base);
    }
    for (; i < total8; i += stride) {
        f8 a = load8(M + i * 8);
        check8(a, i * 8, &scnt, seg_base);
    }

    // ---- tail: phase-0 barrier (all 740 blocks co-resident -> no deadlock;
    // phase 0 finished ~160us ago, so this spin is effectively free) ----
    __syncthreads();                                         // scnt final
    if (threadIdx.x == 0) {
        while (atomicAdd(&g_ready, 0) < (int)gridDim.x) { }
    }
    __syncthreads();
    __threadfence();                                         // acquire

    // ---- scatter OWN segment (exact: all values multiples of 0.125) ----
    const int cnt = (scnt < SEG_CAP) ? scnt : SEG_CAP;
    for (int t = threadIdx.x; t < cnt; t += blockDim.x) {
        unsigned idx = g_list_idx[seg_base + t];
        float val    = g_list_val[seg_base + t];
        int n = (int)(idx >> 14);
        int m = (int)(idx & 16383);
        unsigned long long mask = g_spikemask[n];
        while (mask) {
            int b = __ffsll((long long)mask) - 1;
            atomicAdd(&g_global[(size_t)b * N_PIX + m], val);
            mask &= mask - 1;
        }
    }

    // ---- self-resetting counters: last block through zeroes both ----
    __threadfence();
    __syncthreads();
    if (threadIdx.x == 0) {
        int d = atomicAdd(&g_done, 1);
        if (d == (int)gridDim.x - 1) {       // every block has passed both uses
            g_ready = 0;
            g_done  = 0;
            __threadfence();
        }
    }
}

// ---------------------------------------------------------------------------
// Kernel 2: box convs (separable circular window sums) + fused update.
// Four blocks per batch (32 rows + 3-row halo), smem 38,912 B, 512 threads.
// ---------------------------------------------------------------------------
#define ROWS_PER_BLK 32
#define HALO 3
#define SROWS (ROWS_PER_BLK + 2 * HALO)   // 38

__global__ void __launch_bounds__(512) fused_kernel(
    const float* __restrict__ V0, const float* __restrict__ S0,
    const float* __restrict__ U,
    const float* __restrict__ exc_w_p, const float* __restrict__ inh_w_p,
    const float* __restrict__ p_decay, const float* __restrict__ p_thr,
    const float* __restrict__ p_reset, const float* __restrict__ p_split,
    const float* __restrict__ p_excl,  const float* __restrict__ p_excg,
    const float* __restrict__ p_inhl,  const float* __restrict__ p_inhg,
    const float* __restrict__ p_drop,  const float* __restrict__ p_lower,
    float* __restrict__ out)
{
    extern __shared__ float sm[];
    float* rs7 = sm;                  // horizontal 7-window sums, SROWS x 128
    float* rs5 = sm + SROWS * WDIM;   // horizontal 5-window sums

    const int b  = blockIdx.x >> 2;
    const int r0 = (blockIdx.x & 3) * ROWS_PER_BLK;   // first output row
    const int t  = threadIdx.x;
    const float* S = S0 + (size_t)b * N_PIX;

    // Phase A: horizontal circular window sums for rows r0-3 .. r0+34 (wrapped)
    for (int i = t; i < SROWS * WDIM; i += blockDim.x) {
        int lr = i >> 7, w = i & 127;
        int h = (r0 - HALO + lr) & (HDIM - 1);
        const float* row = S + (h << 7);
        float s7 = 0.f, s5 = 0.f;
        #pragma unroll
        for (int d = -3; d <= 3; d++) {
            float v = row[(w + d) & 127];
            s7 += v;
            if (d >= -2 && d <= 2) s5 += v;
        }
        rs7[i] = s7;
        rs5[i] = s5;
    }
    __syncthreads();

    const float decay = *p_decay, thr = *p_thr, rst = *p_reset, split = *p_split;
    const float excl = *p_excl, excg = *p_excg, inhl = *p_inhl, inhg = *p_inhg;
    const float drop = *p_drop, lower = *p_lower;
    const float w7 = *exc_w_p, w5 = *inh_w_p;       // 1/49, 1/25 (exact f32 from ref)
    const float oms = 1.0f - split;

    float* outV = out;
    float* outS = out + (size_t)BATCH * N_PIX;
    float* outY = out + (size_t)2 * BATCH * N_PIX;

    for (int i = t; i < ROWS_PER_BLK * WDIM; i += blockDim.x) {
        int lr = i >> 7, w = i & 127;
        int h = r0 + lr;

        // Phase B: vertical circular window sums from smem (conflict-free)
        float c7 = 0.f, c5 = 0.f;
        #pragma unroll
        for (int d = -3; d <= 3; d++) {
            int sr = lr + HALO + d;                   // 0..SROWS-1
            c7 += rs7[(sr << 7) + w];
            if (d >= -2 && d <= 2) c5 += rs5[(sr << 7) + w];
        }

        size_t gi = (size_t)b * N_PIX + (h << 7) + w;
        float v0 = V0[gi], u = U[gi], gg = g_global[gi];

        // V = decay*V0 + input_split*U   (non-fused, matches XLA mul+add)
        float V = __fadd_rn(__fmul_rn(decay, v0), __fmul_rn(split, u));
        bool active = V > lower;

        // lateral = excl*conv7 + inhl*conv5 + excg*g + inhg*g
        float conv7 = __fmul_rn(c7, w7);
        float conv5 = __fmul_rn(c5, w5);
        float lat = __fadd_rn(__fmul_rn(excl, conv7), __fmul_rn(inhl, conv5));
        lat = __fadd_rn(lat, __fmul_rn(excg, gg));
        lat = __fadd_rn(lat, __fmul_rn(inhg, gg));

        if (active)
            V = __fadd_rn(__fadd_rn(V, __fmul_rn(oms, u)), lat);
        V = fminf(fmaxf(V, -2.0f), 2.0f);

        float spike = (V > thr) ? 1.0f : 0.0f;

        // deterministic dropout mask: frac(h + 0.7*w) > drop  (non-fused fp32)
        float a = __fadd_rn((float)h, __fmul_rn(0.7f, (float)w));
        float frac = __fsub_rn(a, floorf(a));
        float mask = (frac > drop) ? 1.0f : 0.0f;
        float sp = __fmul_rn(spike, mask);

        if (sp > 0.0f) V = rst;

        float y = fminf(fmaxf(__fmul_rn(__fadd_rn(V, 1.0f), 0.5f), 0.0f), 1.0f);
        y = __fadd_rn(y, __fmul_rn(0.5f, sp));
        y = fminf(fmaxf(y, 0.0f), 1.0f);

        outV[gi] = V;
        outS[gi] = sp;
        outY[gi] = y;
    }
}

// ---------------------------------------------------------------------------
extern "C" void kernel_launch(void* const* d_in, const int* in_sizes, int n_in,
                              void* d_out, int out_size) {
    const float* V0    = (const float*)d_in[0];
    const float* S0    = (const float*)d_in[1];
    const float* U     = (const float*)d_in[2];
    const float* exc_w = (const float*)d_in[3];
    const float* inh_w = (const float*)d_in[4];
    const float* M     = (const float*)d_in[5];
    const float* decay = (const float*)d_in[6];
    const float* thr   = (const float*)d_in[7];
    const float* reset = (const float*)d_in[8];
    const float* split = (const float*)d_in[9];
    const float* excl  = (const float*)d_in[10];
    const float* excg  = (const float*)d_in[11];
    const float* inhl  = (const float*)d_in[12];
    const float* inhg  = (const float*)d_in[13];
    const float* drop  = (const float*)d_in[14];
    const float* lower = (const float*)d_in[15];
    float* out = (float*)d_out;

    scan_kernel<<<SCAN_BLKS, 256>>>(M, S0);

    int smem = 2 * SROWS * WDIM * (int)sizeof(float);    // 38,912 B
    cudaFuncSetAttribute(fused_kernel, cudaFuncAttributeMaxDynamicSharedMemorySize, smem);
    fused_kernel<<<BATCH * 4, 512, smem>>>(V0, S0, U, exc_w, inh_w,
                                           decay, thr, reset, split,
                                           excl, excg, inhl, inhg, drop, lower,
                                           out);
}

// round 16
// speedup vs baseline: 1.0191x; 1.0191x over previous
#include <cuda_runtime.h>
#include <cstdint>

#define HDIM  128
#define WDIM  128
#define N_PIX 16384          // H*W
#define BATCH 64

#define NSM        148
// scan_kernel: 48 regs -> 5 resident blocks/SM at 256 thr; one full wave.
// (R11 vs R13: 1184 vs 740 blocks gave identical 83-84% DRAM -> at ceiling.)
#define SCAN_BLKS  (NSM * 5)     // 740
#define SEG_CAP    2048          // per-block nonzero segment capacity (mean ~177)

// Scratch (allocation-free __device__ globals). mask/g/list/cnt are all fully
// rewritten every launch by scan_kernel -> self-contained, graph-safe.
__device__ unsigned long long g_spikemask[N_PIX];               // bit b set if S0[b, n] != 0
__device__ float              g_global[BATCH * (size_t)N_PIX];  // g[b][m], 4 MB
__device__ unsigned           g_list_idx[SCAN_BLKS * SEG_CAP];  // flat idx into M
__device__ float              g_list_val[SCAN_BLKS * SEG_CAP];
__device__ int                g_cnt[SCAN_BLKS];

// ---------------------------------------------------------------------------
// Kernel 1 (scan): phase 0 builds the spike mask + zeroes g (consumed only by
// later kernels -> no grid sync needed). Phase 1 streams the 1 GiB matrix
// with 256-bit evict-first loads and APPENDS nonzeros to a per-block segment.
// ---------------------------------------------------------------------------
struct f8 { float v[8]; };

__device__ __forceinline__ f8 load8(const float* __restrict__ p) {
    f8 r;
    asm volatile("ld.global.cs.v8.f32 {%0,%1,%2,%3,%4,%5,%6,%7}, [%8];"
                 : "=f"(r.v[0]), "=f"(r.v[1]), "=f"(r.v[2]), "=f"(r.v[3]),
                   "=f"(r.v[4]), "=f"(r.v[5]), "=f"(r.v[6]), "=f"(r.v[7])
                 : "l"(p));
    return r;
}

__device__ __forceinline__ void append_nz(int* scnt, unsigned seg_base,
                                          size_t idx, float val) {
    int s = atomicAdd(scnt, 1);
    if (s < SEG_CAP) {                       // statically impossible to overflow
        g_list_idx[seg_base + s] = (unsigned)idx;
        g_list_val[seg_base + s] = val;
    }
}

__device__ __forceinline__ void check8(const f8& x, size_t base,
                                       int* scnt, unsigned seg_base) {
    unsigned nz = 0;
    #pragma unroll
    for (int j = 0; j < 8; j++) nz |= __float_as_uint(x.v[j]);
    if (nz != 0u) {
        #pragma unroll
        for (int j = 0; j < 8; j++)
            if (x.v[j] != 0.0f) append_nz(scnt, seg_base, base + j, x.v[j]);
    }
}

__global__ void __launch_bounds__(256) scan_kernel(const float* __restrict__ M,
                                                   const float* __restrict__ S0) {
    __shared__ int scnt;
    if (threadIdx.x == 0) scnt = 0;

    const int tid = blockIdx.x * blockDim.x + threadIdx.x;   // 0..189439
    const int nthreads = gridDim.x * blockDim.x;             // 189,440

    // ---- phase 0a: spike mask (65536 workers, disjoint u16 stores) ----
    if (tid < 4 * N_PIX) {
        int n = tid & (N_PIX - 1);
        int q = tid >> 14;                                   // 16-batch chunk
        const float* base = S0 + (size_t)(q * 16) * N_PIX + n;
        unsigned m16 = 0;
        #pragma unroll
        for (int j = 0; j < 16; j++) {
            float s = __ldg(base + (size_t)j * N_PIX);
            if (s != 0.0f) m16 |= (1u << j);
        }
        reinterpret_cast<unsigned short*>(g_spikemask)[4 * n + q] = (unsigned short)m16;
    }
    // ---- phase 0b: zero g (grid-stride; ~1.4 float4 stores per thread) ----
    for (int i = tid; i < BATCH * N_PIX / 4; i += nthreads)
        reinterpret_cast<float4*>(g_global)[i] = make_float4(0.f, 0.f, 0.f, 0.f);

    __syncthreads();                                         // scnt init visible

    // ---- phase 1: stream M, grid-interleaved, 4 in-flight 32B slots ----
    const unsigned seg_base = blockIdx.x * SEG_CAP;
    const size_t total8 = (size_t)N_PIX * N_PIX / 8;         // 33,554,432
    const size_t stride = (size_t)nthreads;                  // 189,440
    size_t i = (size_t)blockIdx.x * blockDim.x + threadIdx.x;

    for (; i + 3 * stride < total8; i += 4 * stride) {
        f8 a = load8(M + (i)              * 8);
        f8 b = load8(M + (i + stride)     * 8);
        f8 c = load8(M + (i + 2 * stride) * 8);
        f8 d = load8(M + (i + 3 * stride) * 8);
        check8(a, (i)              * 8, &scnt, seg_base);
        check8(b, (i + stride)     * 8, &scnt, seg_base);
        check8(c, (i + 2 * stride) * 8, &scnt, seg_base);
        check8(d, (i + 3 * stride) * 8, &scnt, seg_base);
    }
    for (; i < total8; i += stride) {
        f8 a = load8(M + i * 8);
        check8(a, i * 8, &scnt, seg_base);
    }

    __syncthreads();
    if (threadIdx.x == 0)
        g_cnt[blockIdx.x] = (scnt < SEG_CAP) ? scnt : SEG_CAP;
}

// ---------------------------------------------------------------------------
// Kernel 2 (scatter): expand the nonzero list through the spike mask into g.
// ~131K entries * ~6.4 spiking batches -> ~840K exact atomicAdds (all values
// multiples of 0.125 -> order-independent, deterministic).
// ---------------------------------------------------------------------------
__global__ void __launch_bounds__(256) scatter_kernel() {
    const int blk = blockIdx.x;
    const int cnt = g_cnt[blk];
    for (int t = threadIdx.x; t < cnt; t += blockDim.x) {
        unsigned idx = g_list_idx[blk * SEG_CAP + t];
        float val    = g_list_val[blk * SEG_CAP + t];
        int n = (int)(idx >> 14);
        int m = (int)(idx & 16383);
        unsigned long long mask = g_spikemask[n];
        while (mask) {
            int b = __ffsll((long long)mask) - 1;
            atomicAdd(&g_global[(size_t)b * N_PIX + m], val);
            mask &= mask - 1;
        }
    }
}

// ---------------------------------------------------------------------------
// Kernel 3: box convs (separable circular window sums) + fused update.
// Eight blocks per batch (16 rows + 3-row halo), smem 22*128*2*4 = 22,528 B,
// 256 threads. 512 blocks, 8 resident/SM -> ALL co-resident (no wave tail).
// ---------------------------------------------------------------------------
#define ROWS_PER_BLK 16
#define HALO 3
#define SROWS (ROWS_PER_BLK + 2 * HALO)   // 22

__global__ void __launch_bounds__(256) fused_kernel(
    const float* __restrict__ V0, const float* __restrict__ S0,
    const float* __restrict__ U,
    const float* __restrict__ exc_w_p, const float* __restrict__ inh_w_p,
    const float* __restrict__ p_decay, const float* __restrict__ p_thr,
    const float* __restrict__ p_reset, const float* __restrict__ p_split,
    const float* __restrict__ p_excl,  const float* __restrict__ p_excg,
    const float* __restrict__ p_inhl,  const float* __restrict__ p_inhg,
    const float* __restrict__ p_drop,  const float* __restrict__ p_lower,
    float* __restrict__ out)
{
    extern __shared__ float sm[];
    float* rs7 = sm;                  // horizontal 7-window sums, SROWS x 128
    float* rs5 = sm + SROWS * WDIM;   // horizontal 5-window sums

    const int b  = blockIdx.x >> 3;
    const int r0 = (blockIdx.x & 7) * ROWS_PER_BLK;   // first output row
    const int t  = threadIdx.x;
    const float* S = S0 + (size_t)b * N_PIX;

    // Phase A: horizontal circular window sums for rows r0-3 .. r0+18 (wrapped).
    // Sums of 0/1 floats are exact integers -> any summation order bit-identical.
    for (int i = t; i < SROWS * WDIM; i += blockDim.x) {
        int lr = i >> 7, w = i & 127;
        int h = (r0 - HALO + lr) & (HDIM - 1);
        const float* row = S + (h << 7);
        float s5 = 0.f;
        #pragma unroll
        for (int d = -2; d <= 2; d++) s5 += row[(w + d) & 127];
        float s7 = s5 + row[(w - 3) & 127] + row[(w + 3) & 127];
        rs7[i] = s7;
        rs5[i] = s5;
    }
    __syncthreads();

    const float decay = *p_decay, thr = *p_thr, rst = *p_reset, split = *p_split;
    const float excl = *p_excl, excg = *p_excg, inhl = *p_inhl, inhg = *p_inhg;
    const float drop = *p_drop, lower = *p_lower;
    const float w7 = *exc_w_p, w5 = *inh_w_p;       // 1/49, 1/25 (exact f32 from ref)
    const float oms = 1.0f - split;

    float* outV = out;
    float* outS = out + (size_t)BATCH * N_PIX;
    float* outY = out + (size_t)2 * BATCH * N_PIX;

    for (int i = t; i < ROWS_PER_BLK * WDIM; i += blockDim.x) {
        int lr = i >> 7, w = i & 127;
        int h = r0 + lr;

        // Phase B: vertical circular window sums from smem (conflict-free)
        float c7 = 0.f, c5 = 0.f;
        #pragma unroll
        for (int d = -3; d <= 3; d++) {
            int sr = lr + HALO + d;                   // 0..SROWS-1
            c7 += rs7[(sr << 7) + w];
            if (d >= -2 && d <= 2) c5 += rs5[(sr << 7) + w];
        }

        size_t gi = (size_t)b * N_PIX + (h << 7) + w;
        float v0 = V0[gi], u = U[gi], gg = g_global[gi];

        // V = decay*V0 + input_split*U   (non-fused, matches XLA mul+add)
        float V = __fadd_rn(__fmul_rn(decay, v0), __fmul_rn(split, u));
        bool active = V > lower;

        // lateral = excl*conv7 + inhl*conv5 + excg*g + inhg*g
        float conv7 = __fmul_rn(c7, w7);
        float conv5 = __fmul_rn(c5, w5);
        float lat = __fadd_rn(__fmul_rn(excl, conv7), __fmul_rn(inhl, conv5));
        lat = __fadd_rn(lat, __fmul_rn(excg, gg));
        lat = __fadd_rn(lat, __fmul_rn(inhg, gg));

        if (active)
            V = __fadd_rn(__fadd_rn(V, __fmul_rn(oms, u)), lat);
        V = fminf(fmaxf(V, -2.0f), 2.0f);

        float spike = (V > thr) ? 1.0f : 0.0f;

        // deterministic dropout mask: frac(h + 0.7*w) > drop  (non-fused fp32)
        float a = __fadd_rn((float)h, __fmul_rn(0.7f, (float)w));
        float frac = __fsub_rn(a, floorf(a));
        float mask = (frac > drop) ? 1.0f : 0.0f;
        float sp = __fmul_rn(spike, mask);

        if (sp > 0.0f) V = rst;

        float y = fminf(fmaxf(__fmul_rn(__fadd_rn(V, 1.0f), 0.5f), 0.0f), 1.0f);
        y = __fadd_rn(y, __fmul_rn(0.5f, sp));
        y = fminf(fmaxf(y, 0.0f), 1.0f);

        outV[gi] = V;
        outS[gi] = sp;
        outY[gi] = y;
    }
}

// ---------------------------------------------------------------------------
extern "C" void kernel_launch(void* const* d_in, const int* in_sizes, int n_in,
                              void* d_out, int out_size) {
    const float* V0    = (const float*)d_in[0];
    const float* S0    = (const float*)d_in[1];
    const float* U     = (const float*)d_in[2];
    const float* exc_w = (const float*)d_in[3];
    const float* inh_w = (const float*)d_in[4];
    const float* M     = (const float*)d_in[5];
    const float* decay = (const float*)d_in[6];
    const float* thr   = (const float*)d_in[7];
    const float* reset = (const float*)d_in[8];
    const float* split = (const float*)d_in[9];
    const float* excl  = (const float*)d_in[10];
    const float* excg  = (const float*)d_in[11];
    const float* inhl  = (const float*)d_in[12];
    const float* inhg  = (const float*)d_in[13];
    const float* drop  = (const float*)d_in[14];
    const float* lower = (const float*)d_in[15];
    float* out = (float*)d_out;

    scan_kernel<<<SCAN_BLKS, 256>>>(M, S0);
    scatter_kernel<<<SCAN_BLKS, 256>>>();

    int smem = 2 * SROWS * WDIM * (int)sizeof(float);    // 22,528 B
    cudaFuncSetAttribute(fused_kernel, cudaFuncAttributeMaxDynamicSharedMemorySize, smem);
    fused_kernel<<<BATCH * 8, 256, smem>>>(V0, S0, U, exc_w, inh_w,
                                           decay, thr, reset, split,
                                           excl, excg, inhl, inhg, drop, lower,
                                           out);
}

// round 17
// speedup vs baseline: 1.0416x; 1.0221x over previous
#include <cuda_runtime.h>
#include <cstdint>

#define HDIM  128
#define WDIM  128
#define N_PIX 16384          // H*W
#define BATCH 64

#define NSM        148
// scan_kernel: 48 regs -> 5 resident blocks/SM at 256 thr; one full wave.
// (R11 vs R13: 1184 vs 740 blocks gave identical 83-84% DRAM -> at ceiling.)
#define SCAN_BLKS  (NSM * 5)     // 740
#define SEG_CAP    2048          // per-block nonzero segment capacity (mean ~177)

// Scratch (allocation-free __device__ globals). mask/g/list/cnt are all fully
// rewritten every launch by scan_kernel -> self-contained, graph-safe.
__device__ unsigned long long g_spikemask[N_PIX];               // bit b set if S0[b, n] != 0
__device__ float              g_global[BATCH * (size_t)N_PIX];  // g[b][m], 4 MB
__device__ unsigned           g_list_idx[SCAN_BLKS * SEG_CAP];  // flat idx into M
__device__ float              g_list_val[SCAN_BLKS * SEG_CAP];
__device__ int                g_cnt[SCAN_BLKS];

// ---------------------------------------------------------------------------
// Kernel 1 (scan): phase 0 builds the spike mask + zeroes g (consumed only by
// later kernels -> no grid sync needed). Phase 1 streams the 1 GiB matrix
// with 256-bit evict-first loads and APPENDS nonzeros to a per-block segment.
// ---------------------------------------------------------------------------
struct f8 { float v[8]; };

__device__ __forceinline__ f8 load8(const float* __restrict__ p) {
    f8 r;
    asm volatile("ld.global.cs.v8.f32 {%0,%1,%2,%3,%4,%5,%6,%7}, [%8];"
                 : "=f"(r.v[0]), "=f"(r.v[1]), "=f"(r.v[2]), "=f"(r.v[3]),
                   "=f"(r.v[4]), "=f"(r.v[5]), "=f"(r.v[6]), "=f"(r.v[7])
                 : "l"(p));
    return r;
}

__device__ __forceinline__ void append_nz(int* scnt, unsigned seg_base,
                                          size_t idx, float val) {
    int s = atomicAdd(scnt, 1);
    if (s < SEG_CAP) {                       // statically impossible to overflow
        g_list_idx[seg_base + s] = (unsigned)idx;
        g_list_val[seg_base + s] = val;
    }
}

__device__ __forceinline__ void check8(const f8& x, size_t base,
                                       int* scnt, unsigned seg_base) {
    unsigned nz = 0;
    #pragma unroll
    for (int j = 0; j < 8; j++) nz |= __float_as_uint(x.v[j]);
    if (nz != 0u) {
        #pragma unroll
        for (int j = 0; j < 8; j++)
            if (x.v[j] != 0.0f) append_nz(scnt, seg_base, base + j, x.v[j]);
    }
}

__global__ void __launch_bounds__(256) scan_kernel(const float* __restrict__ M,
                                                   const float* __restrict__ S0) {
    __shared__ int scnt;
    if (threadIdx.x == 0) scnt = 0;

    const int tid = blockIdx.x * blockDim.x + threadIdx.x;   // 0..189439
    const int nthreads = gridDim.x * blockDim.x;             // 189,440

    // ---- phase 0a: spike mask (65536 workers, disjoint u16 stores) ----
    if (tid < 4 * N_PIX) {
        int n = tid & (N_PIX - 1);
        int q = tid >> 14;                                   // 16-batch chunk
        const float* base = S0 + (size_t)(q * 16) * N_PIX + n;
        unsigned m16 = 0;
        #pragma unroll
        for (int j = 0; j < 16; j++) {
            float s = __ldg(base + (size_t)j * N_PIX);
            if (s != 0.0f) m16 |= (1u << j);
        }
        reinterpret_cast<unsigned short*>(g_spikemask)[4 * n + q] = (unsigned short)m16;
    }
    // ---- phase 0b: zero g (grid-stride; ~1.4 float4 stores per thread) ----
    for (int i = tid; i < BATCH * N_PIX / 4; i += nthreads)
        reinterpret_cast<float4*>(g_global)[i] = make_float4(0.f, 0.f, 0.f, 0.f);

    __syncthreads();                                         // scnt init visible

    // ---- phase 1: stream M, grid-interleaved, 4 in-flight 32B slots ----
    const unsigned seg_base = blockIdx.x * SEG_CAP;
    const size_t total8 = (size_t)N_PIX * N_PIX / 8;         // 33,554,432
    const size_t stride = (size_t)nthreads;                  // 189,440
    size_t i = (size_t)blockIdx.x * blockDim.x + threadIdx.x;

    for (; i + 3 * stride < total8; i += 4 * stride) {
        f8 a = load8(M + (i)              * 8);
        f8 b = load8(M + (i + stride)     * 8);
        f8 c = load8(M + (i + 2 * stride) * 8);
        f8 d = load8(M + (i + 3 * stride) * 8);
        check8(a, (i)              * 8, &scnt, seg_base);
        check8(b, (i + stride)     * 8, &scnt, seg_base);
        check8(c, (i + 2 * stride) * 8, &scnt, seg_base);
        check8(d, (i + 3 * stride) * 8, &scnt, seg_base);
    }
    for (; i < total8; i += stride) {
        f8 a = load8(M + i * 8);
        check8(a, i * 8, &scnt, seg_base);
    }

    __syncthreads();
    if (threadIdx.x == 0)
        g_cnt[blockIdx.x] = (scnt < SEG_CAP) ? scnt : SEG_CAP;
}

// ---------------------------------------------------------------------------
// Kernel 2 (scatter): expand the nonzero list through the spike mask into g.
// ~131K entries * ~6.4 spiking batches -> ~840K exact atomicAdds (all values
// multiples of 0.125 -> order-independent, deterministic).
// ---------------------------------------------------------------------------
__global__ void __launch_bounds__(256) scatter_kernel() {
    const int blk = blockIdx.x;
    const int cnt = g_cnt[blk];
    for (int t = threadIdx.x; t < cnt; t += blockDim.x) {
        unsigned idx = g_list_idx[blk * SEG_CAP + t];
        float val    = g_list_val[blk * SEG_CAP + t];
        int n = (int)(idx >> 14);
        int m = (int)(idx & 16383);
        unsigned long long mask = g_spikemask[n];
        while (mask) {
            int b = __ffsll((long long)mask) - 1;
            atomicAdd(&g_global[(size_t)b * N_PIX + m], val);
            mask &= mask - 1;
        }
    }
}

// ---------------------------------------------------------------------------
// Kernel 3: box convs + fused update, 4-wide vectorized.
// Eight blocks per batch (16 rows + 3-row halo). Smem: S tile + rs7 + rs5
// = 3*22*128*4 = 33,792 B. 512 blocks x 256 thr, ~6 resident/SM.
// ---------------------------------------------------------------------------
#define ROWS_PER_BLK 16
#define HALO 3
#define SROWS (ROWS_PER_BLK + 2 * HALO)   // 22

__global__ void __launch_bounds__(256) fused_kernel(
    const float* __restrict__ V0, const float* __restrict__ S0,
    const float* __restrict__ U,
    const float* __restrict__ exc_w_p, const float* __restrict__ inh_w_p,
    const float* __restrict__ p_decay, const float* __restrict__ p_thr,
    const float* __restrict__ p_reset, const float* __restrict__ p_split,
    const float* __restrict__ p_excl,  const float* __restrict__ p_excg,
    const float* __restrict__ p_inhl,  const float* __restrict__ p_inhg,
    const float* __restrict__ p_drop,  const float* __restrict__ p_lower,
    float* __restrict__ out)
{
    extern __shared__ float sm[];
    float* smS = sm;                       // staged S rows, SROWS x 128
    float* rs7 = sm + SROWS * WDIM;        // horizontal 7-window sums
    float* rs5 = sm + 2 * SROWS * WDIM;    // horizontal 5-window sums

    const int b  = blockIdx.x >> 3;
    const int r0 = (blockIdx.x & 7) * ROWS_PER_BLK;   // first output row
    const int t  = threadIdx.x;
    const float* S = S0 + (size_t)b * N_PIX;

    // Phase 0: stage S rows r0-3 .. r0+18 (wrapped) into smem, float4 loads.
    for (int i = t; i < SROWS * 32; i += 256) {
        int lr = i >> 5, c = i & 31;
        int h = (r0 - HALO + lr) & (HDIM - 1);
        reinterpret_cast<float4*>(smS)[(lr << 5) + c] =
            reinterpret_cast<const float4*>(S + (h << 7))[c];
    }
    __syncthreads();

    // Phase A: horizontal circular window sums, 4 adjacent outputs/thread.
    // Sums of 0/1 floats are exact integers -> order immaterial (bit-exact).
    for (int q = t; q < SROWS * 32; q += 256) {
        int lr = q >> 5, k = q & 31;
        int w0 = k << 2;
        const float* row = smS + (lr << 7);
        float v[10];
        #pragma unroll
        for (int d = 0; d < 10; d++) v[d] = row[(w0 - 3 + d) & 127];
        float4 r5v, r7v;
        {   // element j: s5 = v[j+1..j+5] (order w-2..w+2), s7 = s5 + v[j] + v[j+6]
            float s50 = v[1]+v[2]+v[3]+v[4]+v[5];
            float s51 = v[2]+v[3]+v[4]+v[5]+v[6];
            float s52 = v[3]+v[4]+v[5]+v[6]+v[7];
            float s53 = v[4]+v[5]+v[6]+v[7]+v[8];
            r5v = make_float4(s50, s51, s52, s53);
            r7v = make_float4(s50 + v[0] + v[6], s51 + v[1] + v[7],
                              s52 + v[2] + v[8], s53 + v[3] + v[9]);
        }
        reinterpret_cast<float4*>(rs7)[(lr << 5) + k] = r7v;
        reinterpret_cast<float4*>(rs5)[(lr << 5) + k] = r5v;
    }
    __syncthreads();

    const float decay = *p_decay, thr = *p_thr, rst = *p_reset, split = *p_split;
    const float excl = *p_excl, excg = *p_excg, inhl = *p_inhl, inhg = *p_inhg;
    const float drop = *p_drop, lower = *p_lower;
    const float w7 = *exc_w_p, w5 = *inh_w_p;       // 1/49, 1/25 (exact f32 from ref)
    const float oms = 1.0f - split;

    float* outV = out;
    float* outS = out + (size_t)BATCH * N_PIX;
    float* outY = out + (size_t)2 * BATCH * N_PIX;

    // Phase B: vertical sums as float4 + elementwise pipeline, 4 px/thread.
    for (int q = t; q < ROWS_PER_BLK * 32; q += 256) {
        int lr = q >> 5, k = q & 31;
        int w0 = k << 2;
        int h = r0 + lr;

        float4 c7 = make_float4(0.f, 0.f, 0.f, 0.f);
        float4 c5 = make_float4(0.f, 0.f, 0.f, 0.f);
        #pragma unroll
        for (int d = -3; d <= 3; d++) {
            int sr = lr + HALO + d;                   // 0..SROWS-1
            float4 x = reinterpret_cast<float4*>(rs7)[(sr << 5) + k];
            c7.x += x.x; c7.y += x.y; c7.z += x.z; c7.w += x.w;
            if (d >= -2 && d <= 2) {
                float4 y = reinterpret_cast<float4*>(rs5)[(sr << 5) + k];
                c5.x += y.x; c5.y += y.y; c5.z += y.z; c5.w += y.w;
            }
        }

        size_t gi = (size_t)b * N_PIX + (h << 7) + w0;
        float4 v04 = *reinterpret_cast<const float4*>(V0 + gi);
        float4 u4  = *reinterpret_cast<const float4*>(U + gi);
        float4 gg4 = *reinterpret_cast<const float4*>(g_global + gi);

        float4 Vo, Sp, Yo;
        #pragma unroll
        for (int j = 0; j < 4; j++) {
            float cc7 = (&c7.x)[j], cc5 = (&c5.x)[j];
            float v0 = (&v04.x)[j], u = (&u4.x)[j], gg = (&gg4.x)[j];
            int w = w0 + j;

            // V = decay*V0 + input_split*U   (non-fused, matches XLA mul+add)
            float V = __fadd_rn(__fmul_rn(decay, v0), __fmul_rn(split, u));
            bool active = V > lower;

            float conv7 = __fmul_rn(cc7, w7);
            float conv5 = __fmul_rn(cc5, w5);
            float lat = __fadd_rn(__fmul_rn(excl, conv7), __fmul_rn(inhl, conv5));
            lat = __fadd_rn(lat, __fmul_rn(excg, gg));
            lat = __fadd_rn(lat, __fmul_rn(inhg, gg));

            if (active)
                V = __fadd_rn(__fadd_rn(V, __fmul_rn(oms, u)), lat);
            V = fminf(fmaxf(V, -2.0f), 2.0f);

            float spike = (V > thr) ? 1.0f : 0.0f;

            float a = __fadd_rn((float)h, __fmul_rn(0.7f, (float)w));
            float frac = __fsub_rn(a, floorf(a));
            float mask = (frac > drop) ? 1.0f : 0.0f;
            float sp = __fmul_rn(spike, mask);

            if (sp > 0.0f) V = rst;

            float y = fminf(fmaxf(__fmul_rn(__fadd_rn(V, 1.0f), 0.5f), 0.0f), 1.0f);
            y = __fadd_rn(y, __fmul_rn(0.5f, sp));
            y = fminf(fmaxf(y, 0.0f), 1.0f);

            (&Vo.x)[j] = V; (&Sp.x)[j] = sp; (&Yo.x)[j] = y;
        }

        *reinterpret_cast<float4*>(outV + gi) = Vo;
        *reinterpret_cast<float4*>(outS + gi) = Sp;
        *reinterpret_cast<float4*>(outY + gi) = Yo;
    }
}

// ---------------------------------------------------------------------------
extern "C" void kernel_launch(void* const* d_in, const int* in_sizes, int n_in,
                              void* d_out, int out_size) {
    const float* V0    = (const float*)d_in[0];
    const float* S0    = (const float*)d_in[1];
    const float* U     = (const float*)d_in[2];
    const float* exc_w = (const float*)d_in[3];
    const float* inh_w = (const float*)d_in[4];
    const float* M     = (const float*)d_in[5];
    const float* decay = (const float*)d_in[6];
    const float* thr   = (const float*)d_in[7];
    const float* reset = (const float*)d_in[8];
    const float* split = (const float*)d_in[9];
    const float* excl  = (const float*)d_in[10];
    const float* excg  = (const float*)d_in[11];
    const float* inhl  = (const float*)d_in[12];
    const float* inhg  = (const float*)d_in[13];
    const float* drop  = (const float*)d_in[14];
    const float* lower = (const float*)d_in[15];
    float* out = (float*)d_out;

    scan_kernel<<<SCAN_BLKS, 256>>>(M, S0);
    scatter_kernel<<<SCAN_BLKS, 256>>>();

    int smem = 3 * SROWS * WDIM * (int)sizeof(float);    // 33,792 B
    cudaFuncSetAttribute(fused_kernel, cudaFuncAttributeMaxDynamicSharedMemorySize, smem);
    fused_kernel<<<BATCH * 8, 256, smem>>>(V0, S0, U, exc_w, inh_w,
                                           decay, thr, reset, split,
                                           excl, excg, inhl, inhg, drop, lower,
                                           out);
}